// round 5
// baseline (speedup 1.0000x reference)
#include <cuda_runtime.h>
#include <cstdint>

constexpr int LDIM = 384;
constexpr int NHW  = 147456;   // 384*384
constexpr int CH   = 64;
constexpr int ND1  = 788;
constexpr int ND2  = 210;
#define EPSV 1e-5f

// ---------------- device scratch (static, no allocations) ----------------
__device__ float g_bufT[CH*NHW];
__device__ float g_bufU[CH*NHW];
__device__ float g_bufX[CH*NHW];
__device__ float g_rs1[ND1];
__device__ float g_rs2[ND2];
__device__ float g_W1af[CH*ND1];
__device__ float g_W1bf[CH*ND1];
__device__ float g_W2f[CH*ND2];
__device__ float g_row[CH*LDIM];
__device__ float g_col[CH*LDIM];
__device__ float g_a1[CH], g_c1[CH], g_a2[CH], g_c2[CH];
__device__ float g_aG[CH], g_cG[CH];
__device__ float g_accS[ND2], g_accQ[ND2];
// conv weights rearranged: [lk 0..9][h 0..1][ci 0..63][tap 0..8][co32]
__device__ float g_wP[10*2*64*9*32];

__device__ __forceinline__ float lrelu(float v){ return fmaxf(v, 0.01f*v); }

__device__ __forceinline__ float wsum(float v){
  #pragma unroll
  for(int o=16;o>0;o>>=1) v += __shfl_down_sync(0xffffffffu, v, o);
  return v;
}

__device__ __forceinline__ uint32_t smem_u32(const void* p){
  uint32_t a;
  asm("{ .reg .u64 t; cvta.to.shared.u64 t, %1; cvt.u32.u64 %0, t; }" : "=r"(a) : "l"(p));
  return a;
}

// ---------------- small kernels ----------------
__global__ void k_zero(){
  int t = threadIdx.x;
  if(t < ND2){ g_accS[t]=0.f; g_accQ[t]=0.f; }
}

// rearrange conv weights: rw layout [lk][co][ci][ky][kx] -> [lk][h][ci][tap][co32]
__global__ void k_prepW(const float* __restrict__ rw){
  int idx = blockIdx.x*256 + threadIdx.x;
  if(idx >= 10*2*64*9*32) return;
  int c32 = idx & 31;
  int tap = (idx>>5) % 9;
  int ci  = (idx/(32*9)) % 64;
  int h   = (idx/(32*9*64)) & 1;
  int lk  = idx/(32*9*64*2);
  g_wP[idx] = rw[ ((lk*CH + h*32 + c32)*CH + ci)*9 + tap ];
}

__global__ void k_stats1d(const float* __restrict__ x1){
  int d = blockIdx.x;
  const float* p = x1 + d*LDIM;
  float s=0.f,q=0.f;
  for(int i=threadIdx.x;i<LDIM;i+=128){ float v=p[i]; s+=v; q+=v*v; }
  __shared__ float ss[4], sq[4];
  s = wsum(s); q = wsum(q);
  int w = threadIdx.x>>5, ln = threadIdx.x&31;
  if(ln==0){ ss[w]=s; sq[w]=q; }
  __syncthreads();
  if(threadIdx.x==0){
    float S=ss[0]+ss[1]+ss[2]+ss[3], Q=sq[0]+sq[1]+sq[2]+sq[3];
    float mu=S/(float)LDIM; float var=Q/(float)LDIM-mu*mu;
    g_rs1[d]=rsqrtf(var+EPSV);
  }
}

__global__ void k_stats2(const float* __restrict__ x2){
  int d = blockIdx.x, seg = blockIdx.y;
  const float* p = x2 + d*NHW + seg*36864;
  float s=0.f,q=0.f;
  for(int i=threadIdx.x;i<36864;i+=256){ float v=p[i]; s+=v; q+=v*v; }
  __shared__ float ss[8], sq[8];
  s=wsum(s); q=wsum(q);
  int w=threadIdx.x>>5, ln=threadIdx.x&31;
  if(ln==0){ ss[w]=s; sq[w]=q; }
  __syncthreads();
  if(threadIdx.x==0){
    float S=0.f,Q=0.f;
    #pragma unroll
    for(int i=0;i<8;i++){S+=ss[i];Q+=sq[i];}
    atomicAdd(&g_accS[d],S); atomicAdd(&g_accQ[d],Q);
  }
}

__global__ void k_fin_rs2(){
  int t=threadIdx.x;
  if(t<ND2){
    float mu = g_accS[t]/(float)NHW;
    float var = g_accQ[t]/(float)NHW - mu*mu;
    g_rs2[t] = rsqrtf(var+EPSV);
    g_accS[t]=0.f; g_accQ[t]=0.f;
  }
}

__global__ void k_foldW1(const float* __restrict__ W1){
  int idx = blockIdx.x*256+threadIdx.x;
  if(idx < CH*ND1){
    int c = idx/ND1, d = idx%ND1;
    float rs = g_rs1[d];
    g_W1af[idx] = W1[c*2*ND1 + d]*rs;
    g_W1bf[idx] = W1[c*2*ND1 + ND1 + d]*rs;
  }
}

__global__ void k_foldW2(const float* __restrict__ W2){
  int idx = blockIdx.x*256+threadIdx.x;
  if(idx < CH*ND2) g_W2f[idx] = W2[idx]*g_rs2[idx%ND2];
}

__global__ void k_rowcol(const float* __restrict__ x1){
  int c = blockIdx.x, i = threadIdx.x;
  const float* wa = g_W1af + c*ND1;
  const float* wb = g_W1bf + c*ND1;
  float r=0.f, cl=0.f;
  for(int d=0; d<ND1; d++){
    float v = x1[d*LDIM + i];
    r  += wa[d]*v;
    cl += wb[d]*v;
  }
  g_row[c*LDIM+i]=r; g_col[c*LDIM+i]=cl;
}

__global__ void k_rcstats(const float* __restrict__ g1, const float* __restrict__ b1){
  int c = blockIdx.x;
  float sr=0.f,qr=0.f,sc=0.f,qc=0.f;
  for(int i=threadIdx.x;i<LDIM;i+=128){
    float r=g_row[c*LDIM+i], cl=g_col[c*LDIM+i];
    sr+=r; qr+=r*r; sc+=cl; qc+=cl*cl;
  }
  __shared__ float sm4[4][4];
  sr=wsum(sr); qr=wsum(qr); sc=wsum(sc); qc=wsum(qc);
  int w=threadIdx.x>>5, ln=threadIdx.x&31;
  if(ln==0){ sm4[w][0]=sr; sm4[w][1]=qr; sm4[w][2]=sc; sm4[w][3]=qc; }
  __syncthreads();
  if(threadIdx.x==0){
    float Sr=0.f,Qr=0.f,Sc=0.f,Qc=0.f;
    #pragma unroll
    for(int i=0;i<4;i++){Sr+=sm4[i][0];Qr+=sm4[i][1];Sc+=sm4[i][2];Qc+=sm4[i][3];}
    float mr=Sr/(float)LDIM, mc=Sc/(float)LDIM;
    float vr=Qr/(float)LDIM-mr*mr, vc=Qc/(float)LDIM-mc*mc;
    float rs=rsqrtf(vr+vc+EPSV);
    float a=g1[c]*rs;
    g_a1[c]=a; g_c1[c]=b1[c]-(mr+mc)*a;
  }
}

// pair2 GEMM with packed f32x2
__global__ void k_pair2(const float* __restrict__ x2){
  extern __shared__ float sm[];
  float* W2T = sm;            // [d][c] 210*64
  float* xs  = sm + 13440;    // 6*256
  int tid=threadIdx.x;
  for(int i=tid;i<13440;i+=256){ int d=i>>6, c=i&63; W2T[i]=g_W2f[c*ND2+d]; }
  int cg = tid>>7, pxl = tid&127;
  int pix0 = blockIdx.x*256;
  unsigned long long a0[16], a1[16];
  #pragma unroll
  for(int p=0;p<16;p++){ a0[p]=0ULL; a1[p]=0ULL; }
  __syncthreads();
  for(int d0=0; d0<ND2; d0+=6){
    for(int i=tid;i<1536;i+=256) xs[i] = x2[(d0 + (i>>8))*NHW + pix0 + (i&255)];
    __syncthreads();
    #pragma unroll
    for(int dd=0;dd<6;dd++){
      float2 v = *(const float2*)(xs + dd*256 + pxl*2);
      unsigned long long dv0, dv1;
      asm("mov.b64 %0, {%1,%1};" : "=l"(dv0) : "f"(v.x));
      asm("mov.b64 %0, {%1,%1};" : "=l"(dv1) : "f"(v.y));
      const unsigned long long* wp = (const unsigned long long*)(W2T + (d0+dd)*64 + cg*32);
      #pragma unroll
      for(int p=0;p<16;p++){
        unsigned long long w2 = wp[p];
        asm("fma.rn.f32x2 %0, %1, %2, %0;" : "+l"(a0[p]) : "l"(w2), "l"(dv0));
        asm("fma.rn.f32x2 %0, %1, %2, %0;" : "+l"(a1[p]) : "l"(w2), "l"(dv1));
      }
    }
    __syncthreads();
  }
  int P = pix0 + pxl*2;
  #pragma unroll
  for(int p=0;p<16;p++){
    float l0,h0,l1,h1;
    asm("mov.b64 {%0,%1}, %2;" : "=f"(l0), "=f"(h0) : "l"(a0[p]));
    asm("mov.b64 {%0,%1}, %2;" : "=f"(l1), "=f"(h1) : "l"(a1[p]));
    int c = cg*32 + 2*p;
    g_bufU[c*NHW + P]       = l0;
    g_bufU[c*NHW + P + 1]   = l1;
    g_bufU[(c+1)*NHW + P]   = h0;
    g_bufU[(c+1)*NHW + P+1] = h1;
  }
}

// pair stage, f32x2: p1 act (separable) + p2 act, then 64x128 channel mix into bufX
__global__ void k_pair(const float* __restrict__ W3){
  extern __shared__ float sm[];
  float* WaT = sm;             // [d][c] stride 66 -> 64*66
  float* WbT = sm + 64*66;     // 64*66
  float* p1s = sm + 2*64*66;   // [c][px] 64*64
  float* p2s = p1s + 4096;     // 64*64
  int tid=threadIdx.x;
  for(int i=tid;i<4096;i+=256){
    int d=i&63, c=i>>6;
    WaT[d*66+c]=W3[c*128+d];
    WbT[d*66+c]=W3[c*128+64+d];
  }
  int P0 = blockIdx.x*64;
  int i0 = P0/LDIM, j0 = P0 - i0*LDIM;   // row constant per block (384%64==0)
  for(int idx=tid;idx<4096;idx+=256){
    int c=idx>>6, px=idx&63;
    float v1 = g_row[c*LDIM+i0] + g_col[c*LDIM+j0+px];
    p1s[idx] = lrelu(g_a1[c]*v1 + g_c1[c]);
    float u = g_bufU[c*NHW + P0 + px];
    p2s[idx] = lrelu(g_a2[c]*u + g_c2[c]);
  }
  __syncthreads();
  int pi=tid&31, cg=tid>>5;
  unsigned long long acc[8];   // [coPair 0..3][px 0..1]
  #pragma unroll
  for(int p=0;p<8;p++) acc[p]=0ULL;
  for(int dd=0;dd<64;dd++){
    float2 v1 = *(const float2*)(p1s + dd*64 + pi*2);
    float2 v2 = *(const float2*)(p2s + dd*64 + pi*2);
    unsigned long long s10,s11,s20,s21;
    asm("mov.b64 %0, {%1,%1};" : "=l"(s10) : "f"(v1.x));
    asm("mov.b64 %0, {%1,%1};" : "=l"(s11) : "f"(v1.y));
    asm("mov.b64 %0, {%1,%1};" : "=l"(s20) : "f"(v2.x));
    asm("mov.b64 %0, {%1,%1};" : "=l"(s21) : "f"(v2.y));
    const unsigned long long* wa = (const unsigned long long*)(WaT + dd*66 + cg*8);
    const unsigned long long* wb = (const unsigned long long*)(WbT + dd*66 + cg*8);
    #pragma unroll
    for(int p=0;p<4;p++){
      unsigned long long wA=wa[p], wB=wb[p];
      asm("fma.rn.f32x2 %0, %1, %2, %0;" : "+l"(acc[p*2  ]) : "l"(wA), "l"(s10));
      asm("fma.rn.f32x2 %0, %1, %2, %0;" : "+l"(acc[p*2  ]) : "l"(wB), "l"(s20));
      asm("fma.rn.f32x2 %0, %1, %2, %0;" : "+l"(acc[p*2+1]) : "l"(wA), "l"(s11));
      asm("fma.rn.f32x2 %0, %1, %2, %0;" : "+l"(acc[p*2+1]) : "l"(wB), "l"(s21));
    }
  }
  #pragma unroll
  for(int p=0;p<4;p++){
    #pragma unroll
    for(int q=0;q<2;q++){
      float lo,hi;
      asm("mov.b64 {%0,%1}, %2;" : "=f"(lo), "=f"(hi) : "l"(acc[p*2+q]));
      int c = cg*8 + 2*p;
      int P = P0 + pi*2 + q;
      g_bufX[c*NHW + P]     = lo;
      g_bufX[(c+1)*NHW + P] = hi;
    }
  }
}

__global__ void k_cstats(const float* __restrict__ buf){
  int c=blockIdx.x, seg=blockIdx.y;
  const float* p = buf + c*NHW + seg*18432;
  float s=0.f,q=0.f;
  for(int i=threadIdx.x;i<18432;i+=256){ float v=p[i]; s+=v; q+=v*v; }
  __shared__ float ss[8], sq[8];
  s=wsum(s); q=wsum(q);
  int w=threadIdx.x>>5, ln=threadIdx.x&31;
  if(ln==0){ ss[w]=s; sq[w]=q; }
  __syncthreads();
  if(threadIdx.x==0){
    float S=0.f,Q=0.f;
    #pragma unroll
    for(int i=0;i<8;i++){S+=ss[i];Q+=sq[i];}
    atomicAdd(&g_accS[c],S); atomicAdd(&g_accQ[c],Q);
  }
}

__global__ void k_fin_affine(const float* __restrict__ gamma, const float* __restrict__ beta,
                             float* __restrict__ aOut, float* __restrict__ cOut){
  int t=threadIdx.x;
  if(t<CH){
    float mu = g_accS[t]/(float)NHW;
    float var = g_accQ[t]/(float)NHW - mu*mu;
    float rs = rsqrtf(var+EPSV);
    float a = gamma[t]*rs;
    aOut[t]=a; cOut[t]=beta[t]-mu*a;
    g_accS[t]=0.f; g_accQ[t]=0.f;
  }
}

__global__ void k_apply(float* __restrict__ buf){
  int c=blockIdx.y;
  int idx=c*NHW + blockIdx.x*256 + threadIdx.x;
  buf[idx] = lrelu(g_aG[c]*buf[idx]+g_cG[c]);
}

__global__ void k_apply_res(const float* __restrict__ u, const float* __restrict__ res,
                            float* __restrict__ o){
  int c=blockIdx.y;
  int idx=c*NHW + blockIdx.x*256 + threadIdx.x;
  o[idx] = lrelu(g_aG[c]*u[idx]+g_cG[c]) + res[idx];
}

// ---------------- conv 3x3 dilated 64->64, f32x2 + cp.async double buffer ----------------
// CTA: 32x16 px (2 px/thread), 32 co (blockIdx.z). Chunks of 4 ci planes, 16 chunks,
// cp.async global->smem prefetch overlapped with compute. Optional input act as
// in-smem transform pass (halo cells re-zeroed: padding must stay 0 after affine).
template<int D>
__device__ __forceinline__ void stage_chunk(const float* __restrict__ in, uint32_t dst,
                                            int c0, int x0, int y0, int tid){
  constexpr int TW=32+2*D, TH=16+2*D, PLSZ=TW*TH;
  #pragma unroll
  for(int cc=0;cc<4;cc++){
    const float* pl = in + (c0+cc)*NHW;
    for(int i=tid;i<PLSZ;i+=256){
      int row=i/TW, col=i-row*TW;
      int gy=y0+row-D, gx=x0+col-D;
      bool ok = ((unsigned)gy<384u) && ((unsigned)gx<384u);
      const float* src = ok ? (pl + gy*LDIM + gx) : in;
      uint32_t sz = ok ? 4u : 0u;
      asm volatile("cp.async.ca.shared.global [%0], [%1], 4, %2;"
        :: "r"(dst + (uint32_t)(cc*PLSZ+i)*4u), "l"(src), "r"(sz) : "memory");
    }
  }
  asm volatile("cp.async.commit_group;" ::: "memory");
}

template<int D>
__global__ void __launch_bounds__(256,2)
k_conv3(const float* __restrict__ in, float* __restrict__ out,
        const float* __restrict__ wP,
        const float* __restrict__ aAff, const float* __restrict__ cAff){
  constexpr int TW=32+2*D, TH=16+2*D, PLSZ=TW*TH;
  constexpr int E = 4*PLSZ;
  extern __shared__ float sm[];
  float* ws    = sm;                 // 18432 floats
  float* tiles = sm + 18432;         // 2*E
  float* aS    = tiles + 2*E;        // 64
  float* cS    = aS + 64;            // 64
  int tid = threadIdx.x;
  int h = blockIdx.z;

  {
    const float4* wg = (const float4*)(wP + h*18432);
    float4* ws4 = (float4*)ws;
    for(int i=tid;i<4608;i+=256) ws4[i]=wg[i];
  }
  bool doAct = (aAff != nullptr);
  if(tid<64){ aS[tid] = doAct ? aAff[tid] : 1.f; cS[tid] = doAct ? cAff[tid] : 0.f; }

  int x = tid&31, ty = tid>>5;
  int x0 = blockIdx.x*32, y0 = blockIdx.y*16;
  uint32_t tbase = smem_u32(tiles);

  unsigned long long a0[16], a1[16];
  #pragma unroll
  for(int p=0;p<16;p++){ a0[p]=0ULL; a1[p]=0ULL; }

  stage_chunk<D>(in, tbase, 0, x0, y0, tid);

  for(int c=0;c<16;c++){
    if(c+1<16){
      stage_chunk<D>(in, tbase + ((c+1)&1)*(E*4), (c+1)*4, x0, y0, tid);
      asm volatile("cp.async.wait_group 1;" ::: "memory");
    } else {
      asm volatile("cp.async.wait_group 0;" ::: "memory");
    }
    __syncthreads();
    float* tile = tiles + (c&1)*E;
    if(doAct){
      // affine+lrelu in SMEM, but padding cells must remain 0 (conv pads the
      // ACTIVATED tensor with zeros) -> re-apply bounds predicate.
      #pragma unroll
      for(int cc=0;cc<4;cc++){
        float aa=aS[c*4+cc], bb=cS[c*4+cc];
        for(int i=tid;i<PLSZ;i+=256){
          int row=i/TW, col=i-row*TW;
          int gy=y0+row-D, gx=x0+col-D;
          bool ok = ((unsigned)gy<384u) && ((unsigned)gx<384u);
          float v = tile[cc*PLSZ+i];
          float t = aa*v + bb;
          tile[cc*PLSZ+i] = ok ? fmaxf(t, 0.01f*t) : 0.f;
        }
      }
      __syncthreads();
    }
    #pragma unroll
    for(int cc=0;cc<4;cc++){
      int ci = c*4+cc;
      const float* tp = tile + cc*PLSZ + ty*TW + x;
      #pragma unroll
      for(int kk=0;kk<9;kk++){
        int ky=kk/3, kx=kk-ky*3;
        float v0 = tp[ky*D*TW + kx*D];
        float v1 = tp[(ky*D+8)*TW + kx*D];
        unsigned long long dv0, dv1;
        asm("mov.b64 %0, {%1,%1};" : "=l"(dv0) : "f"(v0));
        asm("mov.b64 %0, {%1,%1};" : "=l"(dv1) : "f"(v1));
        const ulonglong2* wk = ((const ulonglong2*)ws) + (ci*9+kk)*8;
        #pragma unroll
        for(int p=0;p<8;p++){
          ulonglong2 w2 = wk[p];
          asm("fma.rn.f32x2 %0, %1, %2, %0;" : "+l"(a0[2*p  ]) : "l"(w2.x), "l"(dv0));
          asm("fma.rn.f32x2 %0, %1, %2, %0;" : "+l"(a0[2*p+1]) : "l"(w2.y), "l"(dv0));
          asm("fma.rn.f32x2 %0, %1, %2, %0;" : "+l"(a1[2*p  ]) : "l"(w2.x), "l"(dv1));
          asm("fma.rn.f32x2 %0, %1, %2, %0;" : "+l"(a1[2*p+1]) : "l"(w2.y), "l"(dv1));
        }
      }
    }
    __syncthreads();
  }
  int gy = y0+ty, gx = x0+x;
  float* op = out + (h*32)*NHW + gy*LDIM + gx;
  #pragma unroll
  for(int p=0;p<16;p++){
    float l0,h0,l1,h1;
    asm("mov.b64 {%0,%1}, %2;" : "=f"(l0), "=f"(h0) : "l"(a0[p]));
    asm("mov.b64 {%0,%1}, %2;" : "=f"(l1), "=f"(h1) : "l"(a1[p]));
    op[(2*p  )*NHW]          = l0;
    op[(2*p+1)*NHW]          = h0;
    op[(2*p  )*NHW + 8*LDIM] = l1;
    op[(2*p+1)*NHW + 8*LDIM] = h1;
  }
}

// ---------------- host ----------------
static void launch_conv(int d, const float* in, float* out, const float* w,
                        const float* aA, const float* cA){
  dim3 g(12,24,2);
  if(d==1)      k_conv3<1><<<g,256,93824>>>(in,out,w,aA,cA);
  else if(d==2) k_conv3<2><<<g,256,97280>>>(in,out,w,aA,cA);
  else          k_conv3<4><<<g,256,104960>>>(in,out,w,aA,cA);
}

extern "C" void kernel_launch(void* const* d_in, const int* in_sizes, int n_in,
                              void* d_out, int out_size){
  const float* x1 =(const float*)d_in[0];
  const float* x2 =(const float*)d_in[1];
  const float* W1 =(const float*)d_in[2];
  const float* g1 =(const float*)d_in[3];
  const float* b1 =(const float*)d_in[4];
  const float* W2 =(const float*)d_in[5];
  const float* g2 =(const float*)d_in[6];
  const float* b2 =(const float*)d_in[7];
  const float* W3 =(const float*)d_in[8];
  const float* g3 =(const float*)d_in[9];
  const float* b3 =(const float*)d_in[10];
  const float* rw =(const float*)d_in[11];
  const float* rg =(const float*)d_in[13];
  const float* rbe=(const float*)d_in[14];
  float* outp=(float*)d_out;

  float *bufT,*bufU,*bufX,*wP,*a2p,*c2p,*aGp,*cGp;
  cudaGetSymbolAddress((void**)&bufT, g_bufT);
  cudaGetSymbolAddress((void**)&bufU, g_bufU);
  cudaGetSymbolAddress((void**)&bufX, g_bufX);
  cudaGetSymbolAddress((void**)&wP,   g_wP);
  cudaGetSymbolAddress((void**)&a2p,  g_a2);
  cudaGetSymbolAddress((void**)&c2p,  g_c2);
  cudaGetSymbolAddress((void**)&aGp,  g_aG);
  cudaGetSymbolAddress((void**)&cGp,  g_cG);

  cudaFuncSetAttribute(k_conv3<1>, cudaFuncAttributeMaxDynamicSharedMemorySize, 93824);
  cudaFuncSetAttribute(k_conv3<2>, cudaFuncAttributeMaxDynamicSharedMemorySize, 97280);
  cudaFuncSetAttribute(k_conv3<4>, cudaFuncAttributeMaxDynamicSharedMemorySize, 104960);
  cudaFuncSetAttribute(k_pair2,    cudaFuncAttributeMaxDynamicSharedMemorySize, 61440);
  cudaFuncSetAttribute(k_pair,     cudaFuncAttributeMaxDynamicSharedMemorySize, 66560);

  k_prepW<<<1440,256>>>(rw);
  k_zero<<<1,256>>>();
  k_stats1d<<<788,128>>>(x1);
  k_stats2<<<dim3(210,4),256>>>(x2);
  k_fin_rs2<<<1,256>>>();
  k_foldW1<<<(CH*ND1+255)/256,256>>>(W1);
  k_foldW2<<<(CH*ND2+255)/256,256>>>(W2);
  k_rowcol<<<64,384>>>(x1);
  k_rcstats<<<64,128>>>(g1,b1);
  k_pair2<<<576,256,61440>>>(x2);
  k_cstats<<<dim3(64,8),256>>>(bufU);
  k_fin_affine<<<1,64>>>(g2,b2,a2p,c2p);
  k_pair<<<2304,256,66560>>>(W3);
  k_cstats<<<dim3(64,8),256>>>(bufX);
  k_fin_affine<<<1,64>>>(g3,b3,aGp,cGp);
  k_apply<<<dim3(576,64),256>>>(bufX);   // bufX = activated pair output (residual)

  const int dil[5]={1,2,4,2,1};
  for(int l=0;l<5;l++){
    int d=dil[l];
    const float* w0 = wP + (l*2  )*2*18432;
    const float* w1 = wP + (l*2+1)*2*18432;
    launch_conv(d, bufX, bufT, w0, nullptr, nullptr);
    k_cstats<<<dim3(64,8),256>>>(bufT);
    k_fin_affine<<<1,64>>>(rg + (l*2)*CH, rbe + (l*2)*CH, aGp, cGp);
    launch_conv(d, bufT, bufU, w1, aGp, cGp);
    k_cstats<<<dim3(64,8),256>>>(bufU);
    k_fin_affine<<<1,64>>>(rg + (l*2+1)*CH, rbe + (l*2+1)*CH, aGp, cGp);
    k_apply_res<<<dim3(576,64),256>>>(bufU, bufX, (l==4)? outp : bufX);
  }
}

// round 6
// speedup vs baseline: 1.6976x; 1.6976x over previous
#include <cuda_runtime.h>
#include <cstdint>

constexpr int LDIM = 384;
constexpr int NHW  = 147456;   // 384*384
constexpr int CH   = 64;
constexpr int ND1  = 788;
constexpr int ND2  = 210;
#define EPSV 1e-5f

// ---------------- device scratch (static, no allocations) ----------------
__device__ float g_bufT[CH*NHW];
__device__ float g_bufU[CH*NHW];
__device__ float g_bufX[CH*NHW];
__device__ float g_rs1[ND1];
__device__ float g_rs2[ND2];
__device__ float g_W1af[CH*ND1];
__device__ float g_W1bf[CH*ND1];
__device__ float g_W2f[CH*ND2];
__device__ float g_row[CH*LDIM];
__device__ float g_col[CH*LDIM];
__device__ float g_a1[CH], g_c1[CH], g_a2[CH], g_c2[CH];
__device__ float g_aG[CH], g_cG[CH];
__device__ float g_accS[ND2], g_accQ[ND2];
// conv weights as B-fragment words: [lk][half][tap][cipair 16][72 (64 used)]
// bf16x2: low = ci even, high = ci odd.  hi-split and lo-split arrays.
__device__ uint32_t g_wBh[10*2*9*16*72];
__device__ uint32_t g_wBl[10*2*9*16*72];

__device__ __forceinline__ float lrelu(float v){ return fmaxf(v, 0.01f*v); }

__device__ __forceinline__ float wsum(float v){
  #pragma unroll
  for(int o=16;o>0;o>>=1) v += __shfl_down_sync(0xffffffffu, v, o);
  return v;
}

// split x into bf16 hi + bf16 lo pair words (two elements at once)
__device__ __forceinline__ void bf16split2(float v0, float v1, uint32_t& hp, uint32_t& lp){
  asm("cvt.rn.bf16x2.f32 %0, %1, %2;" : "=r"(hp) : "f"(v1), "f"(v0));
  float h0 = __uint_as_float(hp<<16);
  float h1 = __uint_as_float(hp & 0xffff0000u);
  float l0 = v0 - h0, l1 = v1 - h1;
  asm("cvt.rn.bf16x2.f32 %0, %1, %2;" : "=r"(lp) : "f"(l1), "f"(l0));
}

#define MMA16816(d, a, b0, b1) \
  asm volatile("mma.sync.aligned.m16n8k16.row.col.f32.bf16.bf16.f32 " \
    "{%0,%1,%2,%3}, {%4,%5,%6,%7}, {%8,%9}, {%0,%1,%2,%3};" \
    : "+f"((d)[0]),"+f"((d)[1]),"+f"((d)[2]),"+f"((d)[3]) \
    : "r"((a)[0]),"r"((a)[1]),"r"((a)[2]),"r"((a)[3]), "r"(b0),"r"(b1))

// ---------------- small kernels ----------------
__global__ void k_zero(){
  int t = threadIdx.x;
  if(t < ND2){ g_accS[t]=0.f; g_accQ[t]=0.f; }
}

// pack conv weights into B-fragment layout with bf16 hi/lo split
__global__ void k_prepB(const float* __restrict__ rw){
  int idx = blockIdx.x*256 + threadIdx.x;
  if(idx >= 10*2*9*16*64) return;
  int n   = idx & 63;
  int cp  = (idx>>6) & 15;
  int tap = (idx>>10) % 9;
  int rest= (idx>>10) / 9;       // lk*2+half
  int half= rest & 1;
  int lk  = rest >> 1;
  int ci0 = half*32 + cp*2;
  float w0 = rw[((lk*CH + n)*CH + ci0  )*9 + tap];
  float w1 = rw[((lk*CH + n)*CH + ci0+1)*9 + tap];
  uint32_t hp, lp;
  bf16split2(w0, w1, hp, lp);
  int o = ((rest*9 + tap)*16 + cp)*72 + n;
  g_wBh[o] = hp; g_wBl[o] = lp;
}

__global__ void k_stats1d(const float* __restrict__ x1){
  int d = blockIdx.x;
  const float* p = x1 + d*LDIM;
  float s=0.f,q=0.f;
  for(int i=threadIdx.x;i<LDIM;i+=128){ float v=p[i]; s+=v; q+=v*v; }
  __shared__ float ss[4], sq[4];
  s = wsum(s); q = wsum(q);
  int w = threadIdx.x>>5, ln = threadIdx.x&31;
  if(ln==0){ ss[w]=s; sq[w]=q; }
  __syncthreads();
  if(threadIdx.x==0){
    float S=ss[0]+ss[1]+ss[2]+ss[3], Q=sq[0]+sq[1]+sq[2]+sq[3];
    float mu=S/(float)LDIM; float var=Q/(float)LDIM-mu*mu;
    g_rs1[d]=rsqrtf(var+EPSV);
  }
}

__global__ void k_stats2(const float* __restrict__ x2){
  int d = blockIdx.x, seg = blockIdx.y;
  const float* p = x2 + d*NHW + seg*36864;
  float s=0.f,q=0.f;
  for(int i=threadIdx.x;i<36864;i+=256){ float v=p[i]; s+=v; q+=v*v; }
  __shared__ float ss[8], sq[8];
  s=wsum(s); q=wsum(q);
  int w=threadIdx.x>>5, ln=threadIdx.x&31;
  if(ln==0){ ss[w]=s; sq[w]=q; }
  __syncthreads();
  if(threadIdx.x==0){
    float S=0.f,Q=0.f;
    #pragma unroll
    for(int i=0;i<8;i++){S+=ss[i];Q+=sq[i];}
    atomicAdd(&g_accS[d],S); atomicAdd(&g_accQ[d],Q);
  }
}

__global__ void k_fin_rs2(){
  int t=threadIdx.x;
  if(t<ND2){
    float mu = g_accS[t]/(float)NHW;
    float var = g_accQ[t]/(float)NHW - mu*mu;
    g_rs2[t] = rsqrtf(var+EPSV);
    g_accS[t]=0.f; g_accQ[t]=0.f;
  }
}

__global__ void k_foldW1(const float* __restrict__ W1){
  int idx = blockIdx.x*256+threadIdx.x;
  if(idx < CH*ND1){
    int c = idx/ND1, d = idx%ND1;
    float rs = g_rs1[d];
    g_W1af[idx] = W1[c*2*ND1 + d]*rs;
    g_W1bf[idx] = W1[c*2*ND1 + ND1 + d]*rs;
  }
}

__global__ void k_foldW2(const float* __restrict__ W2){
  int idx = blockIdx.x*256+threadIdx.x;
  if(idx < CH*ND2) g_W2f[idx] = W2[idx]*g_rs2[idx%ND2];
}

__global__ void k_rowcol(const float* __restrict__ x1){
  int c = blockIdx.x, i = threadIdx.x;
  const float* wa = g_W1af + c*ND1;
  const float* wb = g_W1bf + c*ND1;
  float r=0.f, cl=0.f;
  for(int d=0; d<ND1; d++){
    float v = x1[d*LDIM + i];
    r  += wa[d]*v;
    cl += wb[d]*v;
  }
  g_row[c*LDIM+i]=r; g_col[c*LDIM+i]=cl;
}

__global__ void k_rcstats(const float* __restrict__ g1, const float* __restrict__ b1){
  int c = blockIdx.x;
  float sr=0.f,qr=0.f,sc=0.f,qc=0.f;
  for(int i=threadIdx.x;i<LDIM;i+=128){
    float r=g_row[c*LDIM+i], cl=g_col[c*LDIM+i];
    sr+=r; qr+=r*r; sc+=cl; qc+=cl*cl;
  }
  __shared__ float sm4[4][4];
  sr=wsum(sr); qr=wsum(qr); sc=wsum(sc); qc=wsum(qc);
  int w=threadIdx.x>>5, ln=threadIdx.x&31;
  if(ln==0){ sm4[w][0]=sr; sm4[w][1]=qr; sm4[w][2]=sc; sm4[w][3]=qc; }
  __syncthreads();
  if(threadIdx.x==0){
    float Sr=0.f,Qr=0.f,Sc=0.f,Qc=0.f;
    #pragma unroll
    for(int i=0;i<4;i++){Sr+=sm4[i][0];Qr+=sm4[i][1];Sc+=sm4[i][2];Qc+=sm4[i][3];}
    float mr=Sr/(float)LDIM, mc=Sc/(float)LDIM;
    float vr=Qr/(float)LDIM-mr*mr, vc=Qc/(float)LDIM-mc*mc;
    float rs=rsqrtf(vr+vc+EPSV);
    float a=g1[c]*rs;
    g_a1[c]=a; g_c1[c]=b1[c]-(mr+mc)*a;
  }
}

// pair2 GEMM with packed f32x2
__global__ void k_pair2(const float* __restrict__ x2){
  extern __shared__ float sm[];
  float* W2T = sm;            // [d][c] 210*64
  float* xs  = sm + 13440;    // 6*256
  int tid=threadIdx.x;
  for(int i=tid;i<13440;i+=256){ int d=i>>6, c=i&63; W2T[i]=g_W2f[c*ND2+d]; }
  int cg = tid>>7, pxl = tid&127;
  int pix0 = blockIdx.x*256;
  unsigned long long a0[16], a1[16];
  #pragma unroll
  for(int p=0;p<16;p++){ a0[p]=0ULL; a1[p]=0ULL; }
  __syncthreads();
  for(int d0=0; d0<ND2; d0+=6){
    for(int i=tid;i<1536;i+=256) xs[i] = x2[(d0 + (i>>8))*NHW + pix0 + (i&255)];
    __syncthreads();
    #pragma unroll
    for(int dd=0;dd<6;dd++){
      float2 v = *(const float2*)(xs + dd*256 + pxl*2);
      unsigned long long dv0, dv1;
      asm("mov.b64 %0, {%1,%1};" : "=l"(dv0) : "f"(v.x));
      asm("mov.b64 %0, {%1,%1};" : "=l"(dv1) : "f"(v.y));
      const unsigned long long* wp = (const unsigned long long*)(W2T + (d0+dd)*64 + cg*32);
      #pragma unroll
      for(int p=0;p<16;p++){
        unsigned long long w2 = wp[p];
        asm("fma.rn.f32x2 %0, %1, %2, %0;" : "+l"(a0[p]) : "l"(w2), "l"(dv0));
        asm("fma.rn.f32x2 %0, %1, %2, %0;" : "+l"(a1[p]) : "l"(w2), "l"(dv1));
      }
    }
    __syncthreads();
  }
  int P = pix0 + pxl*2;
  #pragma unroll
  for(int p=0;p<16;p++){
    float l0,h0,l1,h1;
    asm("mov.b64 {%0,%1}, %2;" : "=f"(l0), "=f"(h0) : "l"(a0[p]));
    asm("mov.b64 {%0,%1}, %2;" : "=f"(l1), "=f"(h1) : "l"(a1[p]));
    int c = cg*32 + 2*p;
    g_bufU[c*NHW + P]       = l0;
    g_bufU[c*NHW + P + 1]   = l1;
    g_bufU[(c+1)*NHW + P]   = h0;
    g_bufU[(c+1)*NHW + P+1] = h1;
  }
}

// pair stage, f32x2
__global__ void k_pair(const float* __restrict__ W3){
  extern __shared__ float sm[];
  float* WaT = sm;             // [d][c] stride 66
  float* WbT = sm + 64*66;
  float* p1s = sm + 2*64*66;
  float* p2s = p1s + 4096;
  int tid=threadIdx.x;
  for(int i=tid;i<4096;i+=256){
    int d=i&63, c=i>>6;
    WaT[d*66+c]=W3[c*128+d];
    WbT[d*66+c]=W3[c*128+64+d];
  }
  int P0 = blockIdx.x*64;
  int i0 = P0/LDIM, j0 = P0 - i0*LDIM;
  for(int idx=tid;idx<4096;idx+=256){
    int c=idx>>6, px=idx&63;
    float v1 = g_row[c*LDIM+i0] + g_col[c*LDIM+j0+px];
    p1s[idx] = lrelu(g_a1[c]*v1 + g_c1[c]);
    float u = g_bufU[c*NHW + P0 + px];
    p2s[idx] = lrelu(g_a2[c]*u + g_c2[c]);
  }
  __syncthreads();
  int pi=tid&31, cg=tid>>5;
  unsigned long long acc[8];
  #pragma unroll
  for(int p=0;p<8;p++) acc[p]=0ULL;
  for(int dd=0;dd<64;dd++){
    float2 v1 = *(const float2*)(p1s + dd*64 + pi*2);
    float2 v2 = *(const float2*)(p2s + dd*64 + pi*2);
    unsigned long long s10,s11,s20,s21;
    asm("mov.b64 %0, {%1,%1};" : "=l"(s10) : "f"(v1.x));
    asm("mov.b64 %0, {%1,%1};" : "=l"(s11) : "f"(v1.y));
    asm("mov.b64 %0, {%1,%1};" : "=l"(s20) : "f"(v2.x));
    asm("mov.b64 %0, {%1,%1};" : "=l"(s21) : "f"(v2.y));
    const unsigned long long* wa = (const unsigned long long*)(WaT + dd*66 + cg*8);
    const unsigned long long* wb = (const unsigned long long*)(WbT + dd*66 + cg*8);
    #pragma unroll
    for(int p=0;p<4;p++){
      unsigned long long wA=wa[p], wB=wb[p];
      asm("fma.rn.f32x2 %0, %1, %2, %0;" : "+l"(acc[p*2  ]) : "l"(wA), "l"(s10));
      asm("fma.rn.f32x2 %0, %1, %2, %0;" : "+l"(acc[p*2  ]) : "l"(wB), "l"(s20));
      asm("fma.rn.f32x2 %0, %1, %2, %0;" : "+l"(acc[p*2+1]) : "l"(wA), "l"(s11));
      asm("fma.rn.f32x2 %0, %1, %2, %0;" : "+l"(acc[p*2+1]) : "l"(wB), "l"(s21));
    }
  }
  #pragma unroll
  for(int p=0;p<4;p++){
    #pragma unroll
    for(int q=0;q<2;q++){
      float lo,hi;
      asm("mov.b64 {%0,%1}, %2;" : "=f"(lo), "=f"(hi) : "l"(acc[p*2+q]));
      int c = cg*8 + 2*p;
      int P = P0 + pi*2 + q;
      g_bufX[c*NHW + P]     = lo;
      g_bufX[(c+1)*NHW + P] = hi;
    }
  }
}

__global__ void k_cstats(const float* __restrict__ buf){
  int c=blockIdx.x, seg=blockIdx.y;
  const float* p = buf + c*NHW + seg*18432;
  float s=0.f,q=0.f;
  for(int i=threadIdx.x;i<18432;i+=256){ float v=p[i]; s+=v; q+=v*v; }
  __shared__ float ss[8], sq[8];
  s=wsum(s); q=wsum(q);
  int w=threadIdx.x>>5, ln=threadIdx.x&31;
  if(ln==0){ ss[w]=s; sq[w]=q; }
  __syncthreads();
  if(threadIdx.x==0){
    float S=0.f,Q=0.f;
    #pragma unroll
    for(int i=0;i<8;i++){S+=ss[i];Q+=sq[i];}
    atomicAdd(&g_accS[c],S); atomicAdd(&g_accQ[c],Q);
  }
}

__global__ void k_fin_affine(const float* __restrict__ gamma, const float* __restrict__ beta,
                             float* __restrict__ aOut, float* __restrict__ cOut){
  int t=threadIdx.x;
  if(t<CH){
    float mu = g_accS[t]/(float)NHW;
    float var = g_accQ[t]/(float)NHW - mu*mu;
    float rs = rsqrtf(var+EPSV);
    float a = gamma[t]*rs;
    aOut[t]=a; cOut[t]=beta[t]-mu*a;
    g_accS[t]=0.f; g_accQ[t]=0.f;
  }
}

__global__ void k_apply(float* __restrict__ buf){
  int c=blockIdx.y;
  int idx=c*NHW + blockIdx.x*256 + threadIdx.x;
  buf[idx] = lrelu(g_aG[c]*buf[idx]+g_cG[c]);
}

__global__ void k_apply_res(const float* __restrict__ u, const float* __restrict__ res,
                            float* __restrict__ o){
  int c=blockIdx.y;
  int idx=c*NHW + blockIdx.x*256 + threadIdx.x;
  o[idx] = lrelu(g_aG[c]*u[idx]+g_cG[c]) + res[idx];
}

// ---------------- conv 3x3 dilated 64->64 via mma.sync bf16 hi/lo split ----------------
// CTA: 16x16 px tile (M=256: 16 M-atoms = tile rows), N=64 co (8 N-atoms).
// 8 warps: wm=wid>>1 covers M-atoms wm*4..wm*4+3; wn=wid&1 covers co [wn*32,+32).
// K = 64ci x 9tap, processed per half (32 ci) x tap x 2 k16-steps.
// Tiles: bf16x2 (ci even low / odd high), plane stride PLHW ≡ 8 mod 32 (bank-safe).
// B: fragment words [cipair][72], stride 72 ≡ 8 mod 32 (bank-safe), double-buffered.
template<int D>
__global__ void __launch_bounds__(256,2)
k_convM(const float* __restrict__ in, float* __restrict__ out,
        const uint32_t* __restrict__ wBh, const uint32_t* __restrict__ wBl,
        const float* __restrict__ aAff, const float* __restrict__ cAff){
  constexpr int TW2  = 16+2*D;
  constexpr int PLHW = (D==1)?328:((D==2)?424:584);
  constexpr int TILE_W = 16*PLHW;
  extern __shared__ uint32_t smu[];
  uint32_t* tileH = smu;
  uint32_t* tileL = smu + TILE_W;
  uint32_t* Bh    = smu + 2*TILE_W;     // 2 x 1152
  uint32_t* Bl    = Bh + 2*1152;        // 2 x 1152
  float* aS = (float*)(Bl + 2*1152);    // 64
  float* cS = aS + 64;                  // 64

  int tid = threadIdx.x;
  int lane = tid & 31, wid = tid >> 5;
  int wm = wid >> 1, wn = wid & 1;
  int g = lane >> 2, tig = lane & 3;
  int x0 = blockIdx.x*16, y0 = blockIdx.y*16;

  bool doAct = (aAff != nullptr);
  if(tid < 64){ aS[tid] = doAct ? aAff[tid] : 1.f; cS[tid] = doAct ? cAff[tid] : 0.f; }

  float acc[4][4][4];
  #pragma unroll
  for(int j=0;j<4;j++)
    #pragma unroll
    for(int na=0;na<4;na++)
      #pragma unroll
      for(int q=0;q<4;q++) acc[j][na][q]=0.f;

  for(int half=0; half<2; half++){
    __syncthreads();   // tiles free / aS ready
    // stage 32 ci as bf16 hi/lo split tiles
    for(int idx=tid; idx<16*TW2*TW2; idx+=256){
      int cp = idx/(TW2*TW2); int rr = idx - cp*(TW2*TW2);
      int r = rr/TW2, c2 = rr - r*TW2;
      int gy = y0 - D + r, gx = x0 - D + c2;
      float v0=0.f, v1=0.f;
      if(((unsigned)gy<384u) && ((unsigned)gx<384u)){
        int ci0 = half*32 + cp*2;
        v0 = in[ci0*NHW + gy*LDIM + gx];
        v1 = in[(ci0+1)*NHW + gy*LDIM + gx];
        if(doAct){
          float t0 = aS[ci0]*v0 + cS[ci0];   v0 = fmaxf(t0, 0.01f*t0);
          float t1 = aS[ci0+1]*v1 + cS[ci0+1]; v1 = fmaxf(t1, 0.01f*t1);
        }
      }
      uint32_t hp, lp;
      bf16split2(v0, v1, hp, lp);
      int off = cp*PLHW + rr - (rr - r*TW2) + r*TW2 + c2; // = cp*PLHW + r*TW2 + c2
      off = cp*PLHW + r*TW2 + c2;
      tileH[off] = hp; tileL[off] = lp;
    }
    // B for tap 0 of this half
    const uint32_t* bsrcH = wBh + (half*9)*1152;
    const uint32_t* bsrcL = wBl + (half*9)*1152;
    for(int i=tid;i<1152;i+=256){ Bh[i]=bsrcH[i]; Bl[i]=bsrcL[i]; }
    __syncthreads();

    for(int tap=0; tap<9; tap++){
      int buf = tap & 1;
      if(tap < 8){
        const uint32_t* nh = bsrcH + (tap+1)*1152;
        const uint32_t* nl = bsrcL + (tap+1)*1152;
        uint32_t* dh = Bh + (buf^1)*1152;
        uint32_t* dl = Bl + (buf^1)*1152;
        for(int i=tid;i<1152;i+=256){ dh[i]=nh[i]; dl[i]=nl[i]; }
      }
      int ky = tap/3, kx = tap - ky*3;
      #pragma unroll
      for(int kc=0;kc<2;kc++){
        uint32_t AH[4][4], AL[4][4];
        const uint32_t* tb = tileH + (kc*8+tig)*PLHW + (ky*D)*TW2 + kx*D + g;
        #pragma unroll
        for(int j=0;j<4;j++){
          const uint32_t* th = tb + (wm*4+j)*TW2;
          AH[j][0]=th[0]; AH[j][1]=th[8]; AH[j][2]=th[4*PLHW]; AH[j][3]=th[4*PLHW+8];
          const uint32_t* tl = th + TILE_W;
          AL[j][0]=tl[0]; AL[j][1]=tl[8]; AL[j][2]=tl[4*PLHW]; AL[j][3]=tl[4*PLHW+8];
        }
        const uint32_t* bbh = Bh + buf*1152 + (kc*8+tig)*72 + wn*32 + g;
        const uint32_t* bbl = Bl + buf*1152 + (kc*8+tig)*72 + wn*32 + g;
        #pragma unroll
        for(int na=0;na<4;na++){
          uint32_t bh0 = bbh[na*8], bh1 = bbh[na*8 + 4*72];
          uint32_t bl0 = bbl[na*8], bl1 = bbl[na*8 + 4*72];
          #pragma unroll
          for(int j=0;j<4;j++){
            MMA16816(acc[j][na], AH[j], bh0, bh1);
            MMA16816(acc[j][na], AH[j], bl0, bl1);
            MMA16816(acc[j][na], AL[j], bh0, bh1);
          }
        }
      }
      __syncthreads();
    }
  }
  // epilogue: c0:(tx=g, co), c1:(g, co+1), c2:(g+8, co), c3:(g+8, co+1)
  #pragma unroll
  for(int j=0;j<4;j++){
    int gy = y0 + wm*4 + j;
    #pragma unroll
    for(int na=0;na<4;na++){
      int co = wn*32 + na*8 + tig*2;
      float* op = out + co*NHW + gy*LDIM + x0;
      op[g]         = acc[j][na][0];
      op[NHW + g]   = acc[j][na][1];
      op[g+8]       = acc[j][na][2];
      op[NHW + g+8] = acc[j][na][3];
    }
  }
}

// ---------------- host ----------------
static void launch_conv(int d, const float* in, float* out,
                        const uint32_t* wh, const uint32_t* wl,
                        const float* aA, const float* cA){
  dim3 g(24,24);
  if(d==1)      k_convM<1><<<g,256,60928>>>(in,out,wh,wl,aA,cA);
  else if(d==2) k_convM<2><<<g,256,73216>>>(in,out,wh,wl,aA,cA);
  else          k_convM<4><<<g,256,93696>>>(in,out,wh,wl,aA,cA);
}

extern "C" void kernel_launch(void* const* d_in, const int* in_sizes, int n_in,
                              void* d_out, int out_size){
  const float* x1 =(const float*)d_in[0];
  const float* x2 =(const float*)d_in[1];
  const float* W1 =(const float*)d_in[2];
  const float* g1 =(const float*)d_in[3];
  const float* b1 =(const float*)d_in[4];
  const float* W2 =(const float*)d_in[5];
  const float* g2 =(const float*)d_in[6];
  const float* b2 =(const float*)d_in[7];
  const float* W3 =(const float*)d_in[8];
  const float* g3 =(const float*)d_in[9];
  const float* b3 =(const float*)d_in[10];
  const float* rw =(const float*)d_in[11];
  const float* rg =(const float*)d_in[13];
  const float* rbe=(const float*)d_in[14];
  float* outp=(float*)d_out;

  float *bufT,*bufU,*bufX,*a2p,*c2p,*aGp,*cGp;
  uint32_t *wBh,*wBl;
  cudaGetSymbolAddress((void**)&bufT, g_bufT);
  cudaGetSymbolAddress((void**)&bufU, g_bufU);
  cudaGetSymbolAddress((void**)&bufX, g_bufX);
  cudaGetSymbolAddress((void**)&wBh,  g_wBh);
  cudaGetSymbolAddress((void**)&wBl,  g_wBl);
  cudaGetSymbolAddress((void**)&a2p,  g_a2);
  cudaGetSymbolAddress((void**)&c2p,  g_c2);
  cudaGetSymbolAddress((void**)&aGp,  g_aG);
  cudaGetSymbolAddress((void**)&cGp,  g_cG);

  cudaFuncSetAttribute(k_convM<1>, cudaFuncAttributeMaxDynamicSharedMemorySize, 60928);
  cudaFuncSetAttribute(k_convM<2>, cudaFuncAttributeMaxDynamicSharedMemorySize, 73216);
  cudaFuncSetAttribute(k_convM<4>, cudaFuncAttributeMaxDynamicSharedMemorySize, 93696);
  cudaFuncSetAttribute(k_pair2,    cudaFuncAttributeMaxDynamicSharedMemorySize, 61440);
  cudaFuncSetAttribute(k_pair,     cudaFuncAttributeMaxDynamicSharedMemorySize, 66560);

  k_prepB<<<720,256>>>(rw);
  k_zero<<<1,256>>>();
  k_stats1d<<<788,128>>>(x1);
  k_stats2<<<dim3(210,4),256>>>(x2);
  k_fin_rs2<<<1,256>>>();
  k_foldW1<<<(CH*ND1+255)/256,256>>>(W1);
  k_foldW2<<<(CH*ND2+255)/256,256>>>(W2);
  k_rowcol<<<64,384>>>(x1);
  k_rcstats<<<64,128>>>(g1,b1);
  k_pair2<<<576,256,61440>>>(x2);
  k_cstats<<<dim3(64,8),256>>>(bufU);
  k_fin_affine<<<1,64>>>(g2,b2,a2p,c2p);
  k_pair<<<2304,256,66560>>>(W3);
  k_cstats<<<dim3(64,8),256>>>(bufX);
  k_fin_affine<<<1,64>>>(g3,b3,aGp,cGp);
  k_apply<<<dim3(576,64),256>>>(bufX);   // bufX = activated pair output (residual)

  const int dil[5]={1,2,4,2,1};
  for(int l=0;l<5;l++){
    int d=dil[l];
    const uint32_t* wh0 = wBh + (l*2  )*20736;
    const uint32_t* wl0 = wBl + (l*2  )*20736;
    const uint32_t* wh1 = wBh + (l*2+1)*20736;
    const uint32_t* wl1 = wBl + (l*2+1)*20736;
    launch_conv(d, bufX, bufT, wh0, wl0, nullptr, nullptr);
    k_cstats<<<dim3(64,8),256>>>(bufT);
    k_fin_affine<<<1,64>>>(rg + (l*2)*CH, rbe + (l*2)*CH, aGp, cGp);
    launch_conv(d, bufT, bufU, wh1, wl1, aGp, cGp);
    k_cstats<<<dim3(64,8),256>>>(bufU);
    k_fin_affine<<<1,64>>>(rg + (l*2+1)*CH, rbe + (l*2+1)*CH, aGp, cGp);
    k_apply_res<<<dim3(576,64),256>>>(bufU, bufX, (l==4)? outp : bufX);
  }
}